// round 3
// baseline (speedup 1.0000x reference)
#include <cuda_runtime.h>
#include <math.h>

// Problem constants  (reference: C_M, C_Z, C, H = 256, 128, 32, 8)
#define S_DIM 128
#define R_DIM 384
#define CM    256
#define CZ    128
#define H_DIM 8
#define C_DIM 32
#define HC    256          // H*C
#define MROWS (S_DIM*R_DIM)  // 49152
#define EPSLN 1e-5f

// ---------------- scratch (static device globals; no runtime alloc) ----------------
__device__ float g_mn[MROWS * CM];                       // LN(m), [m][cm]
__device__ float g_q [S_DIM*H_DIM*R_DIM*C_DIM];          // [s][h][r][c]
__device__ float g_k [S_DIM*H_DIM*R_DIM*C_DIM];
__device__ float g_v [S_DIM*H_DIM*R_DIM*C_DIM];
__device__ float g_gate[MROWS * HC];                     // sigmoid(mn@Wg+bg), [m][(h,c)]
__device__ float g_bias[H_DIM*R_DIM*R_DIM];              // [h][q][k]
__device__ float g_logits[(size_t)S_DIM*H_DIM*R_DIM*R_DIM]; // [(s,h)][q][k]  (604 MB)
__device__ float g_o[MROWS * HC];                        // gated attention out, [m][(h,c)]

// ---------------- 1. LayerNorm of m ----------------
__global__ void __launch_bounds__(256) ln_m_kernel(const float* __restrict__ m,
                                                   const float* __restrict__ gamma,
                                                   const float* __restrict__ beta) {
    int row = blockIdx.x;          // 0..49151
    int tid = threadIdx.x;         // 0..255
    float x = m[(size_t)row*CM + tid];
    float s = x, s2 = x*x;
    #pragma unroll
    for (int o = 16; o > 0; o >>= 1) {
        s  += __shfl_xor_sync(0xffffffffu, s,  o);
        s2 += __shfl_xor_sync(0xffffffffu, s2, o);
    }
    __shared__ float rs[8], rs2[8];
    int wid = tid >> 5, lane = tid & 31;
    if (lane == 0) { rs[wid] = s; rs2[wid] = s2; }
    __syncthreads();
    if (wid == 0) {
        float a = (lane < 8) ? rs[lane]  : 0.f;
        float b = (lane < 8) ? rs2[lane] : 0.f;
        #pragma unroll
        for (int o = 4; o > 0; o >>= 1) {
            a += __shfl_xor_sync(0xffffffffu, a, o);
            b += __shfl_xor_sync(0xffffffffu, b, o);
        }
        if (lane == 0) { rs[0] = a; rs2[0] = b; }
    }
    __syncthreads();
    float mu  = rs[0]  * (1.f/256.f);
    float var = rs2[0] * (1.f/256.f) - mu*mu;
    g_mn[(size_t)row*CM + tid] = (x - mu) * rsqrtf(var + EPSLN) * gamma[tid] + beta[tid];
}

// ---------------- 2. pair bias: b[h][q][k] = LN(z[q,k,:]) @ Wb[:,h], CZ=128 ----------------
__global__ void __launch_bounds__(256) pair_bias_kernel(const float* __restrict__ z,
                                                        const float* __restrict__ gz,
                                                        const float* __restrict__ bz,
                                                        const float* __restrict__ Wb) {
    int gw   = (blockIdx.x * blockDim.x + threadIdx.x) >> 5;   // one warp per (q,k)
    int lane = threadIdx.x & 31;
    if (gw >= R_DIM * R_DIM) return;
    int qr = gw / R_DIM, kr = gw % R_DIM;
    const float* zp = z + (size_t)gw * CZ;

    float x[4];
    float s = 0.f, s2 = 0.f;
    #pragma unroll
    for (int j = 0; j < 4; j++) {
        x[j] = zp[lane + 32*j];
        s  += x[j];
        s2 += x[j]*x[j];
    }
    #pragma unroll
    for (int o = 16; o > 0; o >>= 1) {
        s  += __shfl_xor_sync(0xffffffffu, s,  o);
        s2 += __shfl_xor_sync(0xffffffffu, s2, o);
    }
    float mu  = s  * (1.f/128.f);
    float var = s2 * (1.f/128.f) - mu*mu;
    float inv = rsqrtf(var + EPSLN);

    float zn[4];
    #pragma unroll
    for (int j = 0; j < 4; j++)
        zn[j] = (x[j] - mu) * inv * gz[lane + 32*j] + bz[lane + 32*j];

    #pragma unroll
    for (int h = 0; h < H_DIM; h++) {
        float p = 0.f;
        #pragma unroll
        for (int j = 0; j < 4; j++)
            p += zn[j] * Wb[(lane + 32*j) * H_DIM + h];
        #pragma unroll
        for (int o = 16; o > 0; o >>= 1) p += __shfl_xor_sync(0xffffffffu, p, o);
        if (lane == 0)
            g_bias[((size_t)h * R_DIM + qr) * R_DIM + kr] = p;
    }
}

// ---------------- 3. QKVG projections: 128x128x8 SGEMM, fused epilogues ----------------
// A = g_mn (49152 x 256), B = W (256 x 256). blockIdx.z selects projection.
__global__ void __launch_bounds__(256) proj_gemm_kernel(const float* __restrict__ Wq,
                                                        const float* __restrict__ Wk,
                                                        const float* __restrict__ Wv,
                                                        const float* __restrict__ Wg,
                                                        const float* __restrict__ bg) {
    const int proj = blockIdx.z;
    const float* B = (proj == 0) ? Wq : (proj == 1) ? Wk : (proj == 2) ? Wv : Wg;

    __shared__ float As[8][128];
    __shared__ float Bs[8][128];

    int tid = threadIdx.x;
    int tx = tid & 15, ty = tid >> 4;
    int m0 = blockIdx.y * 128, n0 = blockIdx.x * 128;

    float acc[8][8];
    #pragma unroll
    for (int i = 0; i < 8; i++)
        #pragma unroll
        for (int j = 0; j < 8; j++) acc[i][j] = 0.f;

    int arow = tid >> 1, ac4 = (tid & 1) * 4;
    int brow = tid >> 5, bc4 = (tid & 31) * 4;
    const float* Ap = g_mn + (size_t)(m0 + arow) * CM + ac4;
    const float* Bp = B    + (size_t)brow * HC + n0 + bc4;

    for (int k0 = 0; k0 < CM; k0 += 8) {
        float4 a = *(const float4*)(Ap + k0);
        float4 b = *(const float4*)(Bp + (size_t)k0 * HC);
        As[ac4+0][arow] = a.x; As[ac4+1][arow] = a.y;
        As[ac4+2][arow] = a.z; As[ac4+3][arow] = a.w;
        *(float4*)&Bs[brow][bc4] = b;
        __syncthreads();
        #pragma unroll
        for (int kk = 0; kk < 8; kk++) {
            float af[8], bf[8];
            #pragma unroll
            for (int i = 0; i < 8; i++) af[i] = As[kk][ty*8 + i];
            #pragma unroll
            for (int j = 0; j < 8; j++) bf[j] = Bs[kk][tx*8 + j];
            #pragma unroll
            for (int i = 0; i < 8; i++)
                #pragma unroll
                for (int j = 0; j < 8; j++) acc[i][j] += af[i] * bf[j];
        }
        __syncthreads();
    }

    #pragma unroll
    for (int i = 0; i < 8; i++) {
        int gm = m0 + ty*8 + i;
        int sI = gm / R_DIM, r = gm % R_DIM;
        #pragma unroll
        for (int j = 0; j < 8; j++) {
            int gn = n0 + tx*8 + j;
            float val = acc[i][j];
            if (proj == 3) {
                val = 1.f / (1.f + expf(-(val + bg[gn])));
                g_gate[(size_t)gm * HC + gn] = val;
            } else {
                int h = gn >> 5, c = gn & 31;
                size_t idx = ((size_t)(sI * H_DIM + h) * R_DIM + r) * C_DIM + c;
                if (proj == 0)      g_q[idx] = val * 0.17677669529663687f; // 1/sqrt(32)
                else if (proj == 1) g_k[idx] = val;
                else                g_v[idx] = val;
            }
        }
    }
}

// ---------------- 4. logits = Q K^T (+bias) : batched 64x64x32 GEMM ----------------
__global__ void __launch_bounds__(256) logits_kernel() {
    int bz = blockIdx.z;                 // (s,h)
    int h  = bz & 7;
    const float* Qb = g_q + (size_t)bz * R_DIM * C_DIM;
    const float* Kb = g_k + (size_t)bz * R_DIM * C_DIM;

    __shared__ float Qs[64][33];
    __shared__ float Ks[64][33];

    int tid = threadIdx.x;
    int q0 = blockIdx.y * 64, k0 = blockIdx.x * 64;

    for (int i = tid; i < 512; i += 256) {
        int row = i >> 3, c4 = (i & 7) << 2;
        float4 qv = *(const float4*)(Qb + (size_t)(q0 + row) * C_DIM + c4);
        float4 kv = *(const float4*)(Kb + (size_t)(k0 + row) * C_DIM + c4);
        Qs[row][c4] = qv.x; Qs[row][c4+1] = qv.y; Qs[row][c4+2] = qv.z; Qs[row][c4+3] = qv.w;
        Ks[row][c4] = kv.x; Ks[row][c4+1] = kv.y; Ks[row][c4+2] = kv.z; Ks[row][c4+3] = kv.w;
    }
    __syncthreads();

    int tx = tid & 15, ty = tid >> 4;
    float acc[4][4];
    #pragma unroll
    for (int i = 0; i < 4; i++)
        #pragma unroll
        for (int j = 0; j < 4; j++) acc[i][j] = 0.f;

    #pragma unroll
    for (int c = 0; c < 32; c++) {
        float qf[4], kf[4];
        #pragma unroll
        for (int i = 0; i < 4; i++) qf[i] = Qs[ty*4 + i][c];
        #pragma unroll
        for (int j = 0; j < 4; j++) kf[j] = Ks[tx*4 + j][c];
        #pragma unroll
        for (int i = 0; i < 4; i++)
            #pragma unroll
            for (int j = 0; j < 4; j++) acc[i][j] += qf[i] * kf[j];
    }

    const float* bb = g_bias + ((size_t)h * R_DIM + q0) * R_DIM + k0;
    #pragma unroll
    for (int i = 0; i < 4; i++) {
        int lq = ty*4 + i;
        #pragma unroll
        for (int j = 0; j < 4; j++) {
            int lk = tx*4 + j;
            g_logits[((size_t)bz * R_DIM + q0 + lq) * R_DIM + k0 + lk] =
                acc[i][j] + bb[(size_t)lq * R_DIM + lk];
        }
    }
}

// ---------------- 5. softmax over k (in place), warp per row ----------------
__global__ void __launch_bounds__(256) softmax_kernel() {
    int gw   = (blockIdx.x * blockDim.x + threadIdx.x) >> 5;
    int lane = threadIdx.x & 31;
    if (gw >= S_DIM * H_DIM * R_DIM) return;
    float* row = g_logits + (size_t)gw * R_DIM;
    float l[12];
    float mx = -1e30f;
    #pragma unroll
    for (int j = 0; j < 12; j++) {
        l[j] = row[lane + 32*j];
        mx = fmaxf(mx, l[j]);
    }
    #pragma unroll
    for (int o = 16; o > 0; o >>= 1) mx = fmaxf(mx, __shfl_xor_sync(0xffffffffu, mx, o));
    float s = 0.f;
    #pragma unroll
    for (int j = 0; j < 12; j++) { l[j] = expf(l[j] - mx); s += l[j]; }
    #pragma unroll
    for (int o = 16; o > 0; o >>= 1) s += __shfl_xor_sync(0xffffffffu, s, o);
    float inv = 1.f / s;
    #pragma unroll
    for (int j = 0; j < 12; j++) row[lane + 32*j] = l[j] * inv;
}

// ---------------- 6. O = P @ V, gated, written to GEMM layout ----------------
__global__ void __launch_bounds__(128) av_kernel() {
    int bz = blockIdx.z;
    int sI = bz >> 3, h = bz & 7;
    const float* Pb = g_logits + (size_t)bz * R_DIM * R_DIM;
    const float* Vb = g_v      + (size_t)bz * R_DIM * C_DIM;

    __shared__ float Ps[128][33];
    __shared__ float Vs[32][33];

    int tid = threadIdx.x;
    int q0 = blockIdx.y * 128;
    int ty = tid >> 3, tx = tid & 7;

    float acc[8][4];
    #pragma unroll
    for (int i = 0; i < 8; i++)
        #pragma unroll
        for (int j = 0; j < 4; j++) acc[i][j] = 0.f;

    for (int kk0 = 0; kk0 < R_DIM; kk0 += 32) {
        for (int i = tid; i < 1024; i += 128) {
            int row = i >> 3, c4 = (i & 7) << 2;
            float4 p = *(const float4*)(Pb + (size_t)(q0 + row) * R_DIM + kk0 + c4);
            Ps[row][c4] = p.x; Ps[row][c4+1] = p.y; Ps[row][c4+2] = p.z; Ps[row][c4+3] = p.w;
        }
        for (int i = tid; i < 256; i += 128) {
            int row = i >> 3, c4 = (i & 7) << 2;
            float4 vv = *(const float4*)(Vb + (size_t)(kk0 + row) * C_DIM + c4);
            Vs[row][c4] = vv.x; Vs[row][c4+1] = vv.y; Vs[row][c4+2] = vv.z; Vs[row][c4+3] = vv.w;
        }
        __syncthreads();
        #pragma unroll
        for (int kk = 0; kk < 32; kk++) {
            float pf[8], vf[4];
            #pragma unroll
            for (int i = 0; i < 8; i++) pf[i] = Ps[ty*8 + i][kk];
            #pragma unroll
            for (int j = 0; j < 4; j++) vf[j] = Vs[kk][tx*4 + j];
            #pragma unroll
            for (int i = 0; i < 8; i++)
                #pragma unroll
                for (int j = 0; j < 4; j++) acc[i][j] += pf[i] * vf[j];
        }
        __syncthreads();
    }

    #pragma unroll
    for (int i = 0; i < 8; i++) {
        int gq = q0 + ty*8 + i;
        size_t mlin = (size_t)sI * R_DIM + gq;
        #pragma unroll
        for (int j = 0; j < 4; j++) {
            int c = tx*4 + j;
            size_t idx = mlin * HC + h * C_DIM + c;
            g_o[idx] = acc[i][j] * g_gate[idx];
        }
    }
}

// ---------------- 7. out = (g*o) @ Wo + bo : 128x128x8 SGEMM ----------------
__global__ void __launch_bounds__(256) out_gemm_kernel(const float* __restrict__ Wo,
                                                       const float* __restrict__ bo,
                                                       float* __restrict__ out) {
    __shared__ float As[8][128];
    __shared__ float Bs[8][128];

    int tid = threadIdx.x;
    int tx = tid & 15, ty = tid >> 4;
    int m0 = blockIdx.y * 128, n0 = blockIdx.x * 128;

    float acc[8][8];
    #pragma unroll
    for (int i = 0; i < 8; i++)
        #pragma unroll
        for (int j = 0; j < 8; j++) acc[i][j] = 0.f;

    int arow = tid >> 1, ac4 = (tid & 1) * 4;
    int brow = tid >> 5, bc4 = (tid & 31) * 4;
    const float* Ap = g_o + (size_t)(m0 + arow) * HC + ac4;
    const float* Bp = Wo  + (size_t)brow * CM + n0 + bc4;

    for (int k0 = 0; k0 < HC; k0 += 8) {
        float4 a = *(const float4*)(Ap + k0);
        float4 b = *(const float4*)(Bp + (size_t)k0 * CM);
        As[ac4+0][arow] = a.x; As[ac4+1][arow] = a.y;
        As[ac4+2][arow] = a.z; As[ac4+3][arow] = a.w;
        *(float4*)&Bs[brow][bc4] = b;
        __syncthreads();
        #pragma unroll
        for (int kk = 0; kk < 8; kk++) {
            float af[8], bf[8];
            #pragma unroll
            for (int i = 0; i < 8; i++) af[i] = As[kk][ty*8 + i];
            #pragma unroll
            for (int j = 0; j < 8; j++) bf[j] = Bs[kk][tx*8 + j];
            #pragma unroll
            for (int i = 0; i < 8; i++)
                #pragma unroll
                for (int j = 0; j < 8; j++) acc[i][j] += af[i] * bf[j];
        }
        __syncthreads();
    }

    #pragma unroll
    for (int i = 0; i < 8; i++) {
        int gm = m0 + ty*8 + i;
        #pragma unroll
        for (int j = 0; j < 8; j++) {
            int gn = n0 + tx*8 + j;
            out[(size_t)gm * CM + gn] = acc[i][j] + bo[gn];
        }
    }
}

// ---------------- launch ----------------
extern "C" void kernel_launch(void* const* d_in, const int* in_sizes, int n_in,
                              void* d_out, int out_size) {
    const float* m      = (const float*)d_in[0];
    const float* z      = (const float*)d_in[1];
    const float* ln_m_g = (const float*)d_in[2];
    const float* ln_m_b = (const float*)d_in[3];
    const float* ln_z_g = (const float*)d_in[4];
    const float* ln_z_b = (const float*)d_in[5];
    const float* Wq     = (const float*)d_in[6];
    const float* Wk     = (const float*)d_in[7];
    const float* Wv     = (const float*)d_in[8];
    const float* Wb     = (const float*)d_in[9];
    const float* Wg     = (const float*)d_in[10];
    const float* bg     = (const float*)d_in[11];
    const float* Wo     = (const float*)d_in[12];
    const float* bo     = (const float*)d_in[13];
    float* out = (float*)d_out;

    // 1. LN(m)
    ln_m_kernel<<<MROWS, 256>>>(m, ln_m_g, ln_m_b);
    // 2. pair bias (warp per (q,k): 147456 warps, CZ=128)
    pair_bias_kernel<<<(R_DIM*R_DIM + 7) / 8, 256>>>(z, ln_z_g, ln_z_b, Wb);
    // 3. Q/K/V/G projections
    proj_gemm_kernel<<<dim3(2, MROWS/128, 4), 256>>>(Wq, Wk, Wv, Wg, bg);
    // 4. logits (batched over 1024 (s,h) pairs)
    logits_kernel<<<dim3(6, 6, S_DIM*H_DIM), 256>>>();
    // 5. softmax (393216 rows, warp each)
    softmax_kernel<<<(S_DIM*H_DIM*R_DIM) / 8, 256>>>();
    // 6. A @ V with gating
    av_kernel<<<dim3(1, 3, S_DIM*H_DIM), 128>>>();
    // 7. output projection
    out_gemm_kernel<<<dim3(2, MROWS/128, 1), 256>>>(Wo, bo, out);
}